// round 4
// baseline (speedup 1.0000x reference)
#include <cuda_runtime.h>
#include <math.h>

// Problem constants
#define BB   8
#define NPT  8192            // unknown points per batch
#define MPT  2048            // known points per batch
#define CCH  256             // features channels
#define CPCH 256             // features_prev channels
#define KD1  512             // C + CP
#define OC   256             // D1 == D2 == 256
#define NPOINTS (BB * NPT)   // 65536
#define BN_EPS 1e-5f

// ---------------- scratch (device globals; no allocs allowed) ----------------
__device__ __align__(16) float g_XT[(size_t)NPOINTS * KD1];      // 128 MB: [point][512]
__device__ __align__(16) float g_Y1[(size_t)NPOINTS * OC];       // 64 MB : raw GEMM1 out [point][256]
__device__ __align__(16) float g_fpT[(size_t)BB * MPT * CPCH];   // 16 MB : features_prev^T [b][m][c]
__device__ int   g_idx[(size_t)NPOINTS * 3];
__device__ float g_wgt[(size_t)NPOINTS * 3];
__device__ __align__(16) float g_stats[4 * 256];                 // sum1,sq1,sum2,sq2
__device__ __align__(16) float g_bnA[2 * 256];                   // per-layer scale
__device__ __align__(16) float g_bnC[2 * 256];                   // per-layer shift

// ---------------- zero stats ----------------
__global__ void k_zero_stats() {
    g_stats[threadIdx.x] = 0.0f;   // blockDim = 1024 == 4*256
}

// ---------------- three_nn: top-3 NN + inverse-distance weights ----------------
__global__ void k_three_nn(const float* __restrict__ xyz, const float* __restrict__ xyzp) {
    const int b = blockIdx.y;
    const int n = blockIdx.x * 256 + threadIdx.x;
    __shared__ float4 sk[MPT];  // (kx,ky,kz, |k|^2)  32 KB
    const float* kp = xyzp + (size_t)b * MPT * 3;
    for (int m = threadIdx.x; m < MPT; m += 256) {
        float kx = kp[3 * m], ky = kp[3 * m + 1], kz = kp[3 * m + 2];
        sk[m] = make_float4(kx, ky, kz, kx * kx + ky * ky + kz * kz);
    }
    __syncthreads();

    const float* up = xyz + (size_t)(b * NPT + n) * 3;
    float ux = up[0], uy = up[1], uz = up[2];
    float squ = ux * ux + uy * uy + uz * uz;

    float d0 = 3.4e38f, d1 = 3.4e38f, d2 = 3.4e38f;
    int i0 = 0, i1 = 0, i2 = 0;
    for (int m = 0; m < MPT; m++) {
        float4 k = sk[m];
        float dot = fmaf(ux, k.x, fmaf(uy, k.y, uz * k.z));
        float dd = squ + k.w - 2.0f * dot;      // matches reference GEMM-form distance
        if (dd < d2) {
            if (dd < d1) {
                d2 = d1; i2 = i1;
                if (dd < d0) { d1 = d0; i1 = i0; d0 = dd; i0 = m; }
                else         { d1 = dd; i1 = m; }
            } else { d2 = dd; i2 = m; }
        }
    }
    float s0 = sqrtf(fmaxf(d0, 0.f));
    float s1 = sqrtf(fmaxf(d1, 0.f));
    float s2 = sqrtf(fmaxf(d2, 0.f));
    float w0 = 1.0f / (s0 + 1e-8f);
    float w1 = 1.0f / (s1 + 1e-8f);
    float w2 = 1.0f / (s2 + 1e-8f);
    float ws = w0 + w1 + w2;
    size_t o = (size_t)(b * NPT + n) * 3;
    g_idx[o] = i0; g_idx[o + 1] = i1; g_idx[o + 2] = i2;
    g_wgt[o] = w0 / ws; g_wgt[o + 1] = w1 / ws; g_wgt[o + 2] = w2 / ws;
}

// ---------------- transpose features_prev [b][c][m] -> g_fpT [b][m][c] ----------------
__global__ void k_transpose_fp(const float* __restrict__ fp) {
    __shared__ float tile[32][33];
    const int b = blockIdx.z;
    const int m0 = blockIdx.x * 32;
    const int c0 = blockIdx.y * 32;
    const float* src = fp + (size_t)b * CPCH * MPT;
    #pragma unroll
    for (int j = 0; j < 32; j += 8)
        tile[threadIdx.y + j][threadIdx.x] =
            src[(size_t)(c0 + threadIdx.y + j) * MPT + m0 + threadIdx.x];
    __syncthreads();
    float* dst = g_fpT + (size_t)b * MPT * CPCH;
    #pragma unroll
    for (int j = 0; j < 32; j += 8)
        dst[(size_t)(m0 + threadIdx.y + j) * CPCH + c0 + threadIdx.x] =
            tile[threadIdx.x][threadIdx.y + j];
}

// ---------------- transpose features [b][c][n] into XT[:, 256:512] ----------------
__global__ void k_feat_to_XT(const float* __restrict__ feat) {
    __shared__ float tile[32][33];
    const int b = blockIdx.z;
    const int n0 = blockIdx.x * 32;
    const int c0 = blockIdx.y * 32;
    const float* src = feat + (size_t)b * CCH * NPT;
    #pragma unroll
    for (int j = 0; j < 32; j += 8)
        tile[threadIdx.y + j][threadIdx.x] =
            src[(size_t)(c0 + threadIdx.y + j) * NPT + n0 + threadIdx.x];
    __syncthreads();
    #pragma unroll
    for (int j = 0; j < 32; j += 8)
        g_XT[(size_t)(b * NPT + n0 + threadIdx.y + j) * KD1 + 256 + c0 + threadIdx.x] =
            tile[threadIdx.x][threadIdx.y + j];
}

// ---------------- 3-point interpolation into XT[:, 0:256]  (1 warp / point) ----------------
__global__ void k_interp() {
    const int gw = (blockIdx.x * blockDim.x + threadIdx.x) >> 5;   // global warp == point
    const int lane = threadIdx.x & 31;
    const int b = gw >> 13;
    const size_t o3 = (size_t)gw * 3;
    const int i0 = g_idx[o3], i1 = g_idx[o3 + 1], i2 = g_idx[o3 + 2];
    const float w0 = g_wgt[o3], w1 = g_wgt[o3 + 1], w2 = g_wgt[o3 + 2];
    const float4* r0 = (const float4*)(g_fpT + ((size_t)b * MPT + i0) * CPCH);
    const float4* r1 = (const float4*)(g_fpT + ((size_t)b * MPT + i1) * CPCH);
    const float4* r2 = (const float4*)(g_fpT + ((size_t)b * MPT + i2) * CPCH);
    float4* out = (float4*)(g_XT + (size_t)gw * KD1);
    #pragma unroll
    for (int j = lane; j < 64; j += 32) {
        float4 a = r0[j], c = r1[j], d = r2[j];
        float4 r;
        r.x = fmaf(w0, a.x, fmaf(w1, c.x, w2 * d.x));
        r.y = fmaf(w0, a.y, fmaf(w1, c.y, w2 * d.y));
        r.z = fmaf(w0, a.z, fmaf(w1, c.z, w2 * d.z));
        r.w = fmaf(w0, a.w, fmaf(w1, c.w, w2 * d.w));
        out[j] = r;
    }
}

// ---------------- fused NT SGEMM ----------------
// PHASE 1: C = XT(65536x512) * w1(256x512)^T + b1 ; write g_Y1 row-major; stats -> g_stats[0..511]
// PHASE 2: A = relu(bnA1*Y1 + bnC1); C = A * w2^T + b2 ; write d_out TRANSPOSED [b][o][n]; stats -> g_stats[512..]
#define TPAD 132
template <int PHASE>
__global__ __launch_bounds__(256, 2) void k_sgemm(const float* __restrict__ W,
                                                  const float* __restrict__ bias,
                                                  float* __restrict__ Cout) {
    constexpr int K = (PHASE == 1) ? KD1 : OC;
    const float* A = (PHASE == 1) ? g_XT : g_Y1;
    float* Cptr = (PHASE == 1) ? g_Y1 : Cout;

    __shared__ float As[2][16][TPAD];
    __shared__ float Bs[2][16][TPAD];

    const int tid = threadIdx.x;
    const int tx = tid & 15;          // output-channel group
    const int ty = tid >> 4;          // row group
    const int m0 = blockIdx.x * 128;  // point rows
    const int o0 = blockIdx.y * 128;  // output channels

    const int lrow = tid >> 2;        // 0..63
    const int lkq = tid & 3;          // 0..3 (k quad)
    const float* Ap0 = A + (size_t)(m0 + lrow) * K + lkq * 4;
    const float* Ap1 = Ap0 + (size_t)64 * K;
    const float* Wp0 = W + (size_t)(o0 + lrow) * K + lkq * 4;
    const float* Wp1 = Wp0 + (size_t)64 * K;

    float4 ra0, ra1, rw0, rw1;
    float acc[8][8];
    #pragma unroll
    for (int i = 0; i < 8; i++)
        #pragma unroll
        for (int j = 0; j < 8; j++) acc[i][j] = 0.0f;

    constexpr int NT = K / 16;

    // ---- tile 0 loads ----
    {
        ra0 = *(const float4*)Ap0;
        ra1 = *(const float4*)Ap1;
        rw0 = *(const float4*)Wp0;
        rw1 = *(const float4*)Wp1;
        if (PHASE == 2) {
            const float4 a4 = *(const float4*)&g_bnA[lkq * 4];
            const float4 c4 = *(const float4*)&g_bnC[lkq * 4];
            ra0.x = fmaxf(fmaf(a4.x, ra0.x, c4.x), 0.f);
            ra0.y = fmaxf(fmaf(a4.y, ra0.y, c4.y), 0.f);
            ra0.z = fmaxf(fmaf(a4.z, ra0.z, c4.z), 0.f);
            ra0.w = fmaxf(fmaf(a4.w, ra0.w, c4.w), 0.f);
            ra1.x = fmaxf(fmaf(a4.x, ra1.x, c4.x), 0.f);
            ra1.y = fmaxf(fmaf(a4.y, ra1.y, c4.y), 0.f);
            ra1.z = fmaxf(fmaf(a4.z, ra1.z, c4.z), 0.f);
            ra1.w = fmaxf(fmaf(a4.w, ra1.w, c4.w), 0.f);
        }
        const int kb = lkq * 4;
        As[0][kb + 0][lrow] = ra0.x; As[0][kb + 1][lrow] = ra0.y;
        As[0][kb + 2][lrow] = ra0.z; As[0][kb + 3][lrow] = ra0.w;
        As[0][kb + 0][lrow + 64] = ra1.x; As[0][kb + 1][lrow + 64] = ra1.y;
        As[0][kb + 2][lrow + 64] = ra1.z; As[0][kb + 3][lrow + 64] = ra1.w;
        Bs[0][kb + 0][lrow] = rw0.x; Bs[0][kb + 1][lrow] = rw0.y;
        Bs[0][kb + 2][lrow] = rw0.z; Bs[0][kb + 3][lrow] = rw0.w;
        Bs[0][kb + 0][lrow + 64] = rw1.x; Bs[0][kb + 1][lrow + 64] = rw1.y;
        Bs[0][kb + 2][lrow + 64] = rw1.z; Bs[0][kb + 3][lrow + 64] = rw1.w;
    }
    __syncthreads();

    for (int t = 0; t < NT; t++) {
        const int buf = t & 1;
        if (t + 1 < NT) {
            const int off = (t + 1) * 16;
            ra0 = *(const float4*)(Ap0 + off);
            ra1 = *(const float4*)(Ap1 + off);
            rw0 = *(const float4*)(Wp0 + off);
            rw1 = *(const float4*)(Wp1 + off);
            if (PHASE == 2) {
                const float4 a4 = *(const float4*)&g_bnA[off + lkq * 4];
                const float4 c4 = *(const float4*)&g_bnC[off + lkq * 4];
                ra0.x = fmaxf(fmaf(a4.x, ra0.x, c4.x), 0.f);
                ra0.y = fmaxf(fmaf(a4.y, ra0.y, c4.y), 0.f);
                ra0.z = fmaxf(fmaf(a4.z, ra0.z, c4.z), 0.f);
                ra0.w = fmaxf(fmaf(a4.w, ra0.w, c4.w), 0.f);
                ra1.x = fmaxf(fmaf(a4.x, ra1.x, c4.x), 0.f);
                ra1.y = fmaxf(fmaf(a4.y, ra1.y, c4.y), 0.f);
                ra1.z = fmaxf(fmaf(a4.z, ra1.z, c4.z), 0.f);
                ra1.w = fmaxf(fmaf(a4.w, ra1.w, c4.w), 0.f);
            }
        }
        #pragma unroll
        for (int kk = 0; kk < 16; kk++) {
            float av[8], bv[8];
            *(float4*)&av[0] = *(const float4*)&As[buf][kk][ty * 8];
            *(float4*)&av[4] = *(const float4*)&As[buf][kk][ty * 8 + 4];
            *(float4*)&bv[0] = *(const float4*)&Bs[buf][kk][tx * 8];
            *(float4*)&bv[4] = *(const float4*)&Bs[buf][kk][tx * 8 + 4];
            #pragma unroll
            for (int i = 0; i < 8; i++)
                #pragma unroll
                for (int j = 0; j < 8; j++)
                    acc[i][j] = fmaf(av[i], bv[j], acc[i][j]);
        }
        if (t + 1 < NT) {
            const int nb = buf ^ 1;
            const int kb = lkq * 4;
            As[nb][kb + 0][lrow] = ra0.x; As[nb][kb + 1][lrow] = ra0.y;
            As[nb][kb + 2][lrow] = ra0.z; As[nb][kb + 3][lrow] = ra0.w;
            As[nb][kb + 0][lrow + 64] = ra1.x; As[nb][kb + 1][lrow + 64] = ra1.y;
            As[nb][kb + 2][lrow + 64] = ra1.z; As[nb][kb + 3][lrow + 64] = ra1.w;
            Bs[nb][kb + 0][lrow] = rw0.x; Bs[nb][kb + 1][lrow] = rw0.y;
            Bs[nb][kb + 2][lrow] = rw0.z; Bs[nb][kb + 3][lrow] = rw0.w;
            Bs[nb][kb + 0][lrow + 64] = rw1.x; Bs[nb][kb + 1][lrow + 64] = rw1.y;
            Bs[nb][kb + 2][lrow + 64] = rw1.z; Bs[nb][kb + 3][lrow + 64] = rw1.w;
            __syncthreads();
        }
    }

    // bias (pre-BN value, as in reference)
    #pragma unroll
    for (int j = 0; j < 8; j++) {
        const float bb = bias[o0 + tx * 8 + j];
        #pragma unroll
        for (int i = 0; i < 8; i++) acc[i][j] += bb;
    }

    // write result
    if (PHASE == 1) {
        #pragma unroll
        for (int i = 0; i < 8; i++) {
            float4* p = (float4*)(Cptr + (size_t)(m0 + ty * 8 + i) * OC + o0 + tx * 8);
            p[0] = make_float4(acc[i][0], acc[i][1], acc[i][2], acc[i][3]);
            p[1] = make_float4(acc[i][4], acc[i][5], acc[i][6], acc[i][7]);
        }
    } else {
        const int mg = m0 + ty * 8;
        const int b = mg >> 13;
        const int n = mg & (NPT - 1);
        #pragma unroll
        for (int j = 0; j < 8; j++) {
            const int o = o0 + tx * 8 + j;
            float* p = Cptr + ((size_t)b * OC + o) * NPT + n;
            *(float4*)p = make_float4(acc[0][j], acc[1][j], acc[2][j], acc[3][j]);
            *(float4*)(p + 4) = make_float4(acc[4][j], acc[5][j], acc[6][j], acc[7][j]);
        }
    }

    // BN stats: block-reduce then atomics
    __syncthreads();
    float* smS = &As[0][0][0];
    float* smQ = &As[1][0][0];
    if (tid < 128) { smS[tid] = 0.f; smQ[tid] = 0.f; }
    __syncthreads();
    #pragma unroll
    for (int j = 0; j < 8; j++) {
        float s = 0.f, q = 0.f;
        #pragma unroll
        for (int i = 0; i < 8; i++) { s += acc[i][j]; q = fmaf(acc[i][j], acc[i][j], q); }
        atomicAdd(&smS[tx * 8 + j], s);
        atomicAdd(&smQ[tx * 8 + j], q);
    }
    __syncthreads();
    float* stats = g_stats + ((PHASE == 1) ? 0 : 512);
    if (tid < 128) {
        atomicAdd(&stats[o0 + tid], smS[tid]);
        atomicAdd(&stats[256 + o0 + tid], smQ[tid]);
    }
}

// ---------------- BN finalize: stats -> (a, c) ----------------
__global__ void k_bn_final(const float* __restrict__ g, const float* __restrict__ beta, int layer) {
    const int c = threadIdx.x;  // 256
    const float invn = 1.0f / (float)NPOINTS;
    const float s = g_stats[layer * 512 + c];
    const float q = g_stats[layer * 512 + 256 + c];
    const float mean = s * invn;
    const float var = q * invn - mean * mean;
    const float a = g[c] * rsqrtf(var + BN_EPS);
    g_bnA[layer * 256 + c] = a;
    g_bnC[layer * 256 + c] = beta[c] - mean * a;
}

// ---------------- final in-place BN2 + ReLU over d_out [b][c][n] ----------------
__global__ void k_bn_relu_out(float* __restrict__ out) {
    const size_t i = (size_t)blockIdx.x * blockDim.x + threadIdx.x;   // float4 index
    const int ch = (int)((i >> 11) & 255);                            // (i*4 >> 13) & 255
    const float a = g_bnA[256 + ch];
    const float c = g_bnC[256 + ch];
    float4 v = ((float4*)out)[i];
    v.x = fmaxf(fmaf(a, v.x, c), 0.f);
    v.y = fmaxf(fmaf(a, v.y, c), 0.f);
    v.z = fmaxf(fmaf(a, v.z, c), 0.f);
    v.w = fmaxf(fmaf(a, v.w, c), 0.f);
    ((float4*)out)[i] = v;
}

// ---------------- launch ----------------
extern "C" void kernel_launch(void* const* d_in, const int* in_sizes, int n_in,
                              void* d_out, int out_size) {
    const float* xyz   = (const float*)d_in[0];
    const float* xyzp  = (const float*)d_in[1];
    const float* feat  = (const float*)d_in[2];
    const float* featp = (const float*)d_in[3];
    const float* w1    = (const float*)d_in[4];
    const float* b1    = (const float*)d_in[5];
    const float* g1    = (const float*)d_in[6];
    const float* be1   = (const float*)d_in[7];
    const float* w2    = (const float*)d_in[8];
    const float* b2    = (const float*)d_in[9];
    const float* g2    = (const float*)d_in[10];
    const float* be2   = (const float*)d_in[11];
    float* out = (float*)d_out;

    k_zero_stats<<<1, 1024>>>();
    k_three_nn<<<dim3(NPT / 256, BB), 256>>>(xyz, xyzp);
    k_transpose_fp<<<dim3(MPT / 32, CPCH / 32, BB), dim3(32, 8)>>>(featp);
    k_feat_to_XT<<<dim3(NPT / 32, CCH / 32, BB), dim3(32, 8)>>>(feat);
    k_interp<<<(NPOINTS * 32) / 256, 256>>>();

    k_sgemm<1><<<dim3(NPOINTS / 128, OC / 128), 256>>>(w1, b1, nullptr);
    k_bn_final<<<1, 256>>>(g1, be1, 0);
    k_sgemm<2><<<dim3(NPOINTS / 128, OC / 128), 256>>>(w2, b2, out);
    k_bn_final<<<1, 256>>>(g2, be2, 1);
    k_bn_relu_out<<<(NPOINTS * OC / 4) / 256, 256>>>(out);
}

// round 8
// speedup vs baseline: 2.3025x; 2.3025x over previous
#include <cuda_runtime.h>
#include <cstdint>
#include <math.h>

// Problem constants
#define BB   8
#define NPT  8192
#define MPT  2048
#define CCH  256
#define CPCH 256
#define KD1  512
#define OC   256
#define NPOINTS (BB * NPT)   // 65536
#define BN_EPS 1e-5f

#if defined(__CUDA_ARCH_FEAT_SM103_ALL) || defined(__CUDA_ARCH_FEAT_SM100_ALL)
#define HAS_TCGEN05 1
#else
#define HAS_TCGEN05 0
#endif

// ---------------- scratch (device globals; no allocs allowed) ----------------
__device__ __align__(16) float g_XT[(size_t)NPOINTS * KD1];      // [point][512]
__device__ __align__(16) float g_Y1[(size_t)NPOINTS * OC];       // [channel][65536]  (transposed!)
__device__ __align__(16) float g_fpT[(size_t)BB * MPT * CPCH];   // features_prev^T [b][m][c]
__device__ int   g_idx[(size_t)NPOINTS * 3];
__device__ float g_wgt[(size_t)NPOINTS * 3];
__device__ __align__(16) float g_stats[4 * 256];                 // sum1,sq1,sum2,sq2
__device__ __align__(16) float g_bnA[2 * 256];
__device__ __align__(16) float g_bnC[2 * 256];

// ---------------- helpers ----------------
__device__ __forceinline__ uint32_t smem_u32(const void* p) {
    uint32_t a;
    asm("{ .reg .u64 t; cvta.to.shared.u64 t, %1; cvt.u32.u64 %0, t; }" : "=r"(a) : "l"(p));
    return a;
}
#define SWZ(o) ((o) ^ (((o) >> 3) & 0x70))
__device__ __forceinline__ uint32_t f2tf(float f) {
    uint32_t r; asm("cvt.rna.tf32.f32 %0, %1;" : "=r"(r) : "f"(f)); return r;
}

#if HAS_TCGEN05
__device__ __forceinline__ uint32_t elect1() {
    uint32_t p;
    asm volatile("{ .reg .pred p; elect.sync _|p, 0xFFFFFFFF; selp.b32 %0,1,0,p; }" : "=r"(p));
    return p;
}
static constexpr uint64_t DESC_BASE =
    (2ull << 61) | (1ull << 46) | (64ull << 32) | (1ull << 16);   // SW128, Blackwell, SBO=64, LBO=1
__device__ __forceinline__ uint64_t mk_desc(uint32_t a) {
    return DESC_BASE | (uint64_t)((a >> 4) & 0x3FFF);
}
__device__ __forceinline__ void mma_tf32(uint32_t d, uint64_t a, uint64_t b,
                                         uint32_t idesc, uint32_t en) {
    asm volatile(
        "{\n\t.reg .pred p;\n\tsetp.ne.u32 p, %5, 0;\n\t"
        "tcgen05.mma.cta_group::1.kind::tf32 [%0], %1, %2, %3, {%4, %4, %4, %4}, p;\n\t}"
        :: "r"(d), "l"(a), "l"(b), "r"(idesc), "r"(0u), "r"(en) : "memory");
}
__device__ __forceinline__ void mbar_wait(uint32_t mbar, uint32_t parity) {
    asm volatile(
        "{\n\t.reg .pred P;\n\tLW_%=:\n\t"
        "mbarrier.try_wait.parity.acquire.cta.shared::cta.b64 P, [%0], %1, 0x989680;\n\t"
        "@P bra.uni LD_%=;\n\tbra.uni LW_%=;\n\tLD_%=:\n\t}"
        :: "r"(mbar), "r"(parity) : "memory");
}
__device__ __forceinline__ void ldtm32(uint32_t* r, uint32_t addr) {
    asm volatile(
        "tcgen05.ld.sync.aligned.32x32b.x32.b32 "
        "{%0, %1, %2, %3, %4, %5, %6, %7, %8, %9, %10, %11, %12, %13, %14, %15, "
        " %16, %17, %18, %19, %20, %21, %22, %23, %24, %25, %26, %27, %28, %29, %30, %31}, [%32];"
        : "=r"(r[0]), "=r"(r[1]), "=r"(r[2]), "=r"(r[3]), "=r"(r[4]), "=r"(r[5]),
          "=r"(r[6]), "=r"(r[7]), "=r"(r[8]), "=r"(r[9]), "=r"(r[10]), "=r"(r[11]),
          "=r"(r[12]), "=r"(r[13]), "=r"(r[14]), "=r"(r[15]), "=r"(r[16]), "=r"(r[17]),
          "=r"(r[18]), "=r"(r[19]), "=r"(r[20]), "=r"(r[21]), "=r"(r[22]), "=r"(r[23]),
          "=r"(r[24]), "=r"(r[25]), "=r"(r[26]), "=r"(r[27]), "=r"(r[28]), "=r"(r[29]),
          "=r"(r[30]), "=r"(r[31])
        : "r"(addr));
}
#endif  // HAS_TCGEN05

// ---------------- zero stats ----------------
__global__ void k_zero_stats() { g_stats[threadIdx.x] = 0.0f; }

// ---------------- three_nn ----------------
__global__ void k_three_nn(const float* __restrict__ xyz, const float* __restrict__ xyzp) {
    const int b = blockIdx.y;
    const int n = blockIdx.x * 256 + threadIdx.x;
    __shared__ float4 sk[MPT];
    const float* kp = xyzp + (size_t)b * MPT * 3;
    for (int m = threadIdx.x; m < MPT; m += 256) {
        float kx = kp[3 * m], ky = kp[3 * m + 1], kz = kp[3 * m + 2];
        sk[m] = make_float4(kx, ky, kz, kx * kx + ky * ky + kz * kz);
    }
    __syncthreads();
    const float* up = xyz + (size_t)(b * NPT + n) * 3;
    float ux = up[0], uy = up[1], uz = up[2];
    float squ = ux * ux + uy * uy + uz * uz;
    float d0 = 3.4e38f, d1 = 3.4e38f, d2 = 3.4e38f;
    int i0 = 0, i1 = 0, i2 = 0;
    for (int m = 0; m < MPT; m++) {
        float4 k = sk[m];
        float dot = fmaf(ux, k.x, fmaf(uy, k.y, uz * k.z));
        float dd = squ + k.w - 2.0f * dot;
        if (dd < d2) {
            if (dd < d1) {
                d2 = d1; i2 = i1;
                if (dd < d0) { d1 = d0; i1 = i0; d0 = dd; i0 = m; }
                else         { d1 = dd; i1 = m; }
            } else { d2 = dd; i2 = m; }
        }
    }
    float s0 = sqrtf(fmaxf(d0, 0.f)), s1 = sqrtf(fmaxf(d1, 0.f)), s2 = sqrtf(fmaxf(d2, 0.f));
    float w0 = 1.0f / (s0 + 1e-8f), w1 = 1.0f / (s1 + 1e-8f), w2 = 1.0f / (s2 + 1e-8f);
    float ws = w0 + w1 + w2;
    size_t o = (size_t)(b * NPT + n) * 3;
    g_idx[o] = i0; g_idx[o + 1] = i1; g_idx[o + 2] = i2;
    g_wgt[o] = w0 / ws; g_wgt[o + 1] = w1 / ws; g_wgt[o + 2] = w2 / ws;
}

// ---------------- transpose features_prev [b][c][m] -> g_fpT [b][m][c] ----------------
__global__ void k_transpose_fp(const float* __restrict__ fp) {
    __shared__ float tile[32][33];
    const int b = blockIdx.z, m0 = blockIdx.x * 32, c0 = blockIdx.y * 32;
    const float* src = fp + (size_t)b * CPCH * MPT;
    #pragma unroll
    for (int j = 0; j < 32; j += 8)
        tile[threadIdx.y + j][threadIdx.x] =
            src[(size_t)(c0 + threadIdx.y + j) * MPT + m0 + threadIdx.x];
    __syncthreads();
    float* dst = g_fpT + (size_t)b * MPT * CPCH;
    #pragma unroll
    for (int j = 0; j < 32; j += 8)
        dst[(size_t)(m0 + threadIdx.y + j) * CPCH + c0 + threadIdx.x] =
            tile[threadIdx.x][threadIdx.y + j];
}

// ---------------- transpose features into XT[:, 256:512] ----------------
__global__ void k_feat_to_XT(const float* __restrict__ feat) {
    __shared__ float tile[32][33];
    const int b = blockIdx.z, n0 = blockIdx.x * 32, c0 = blockIdx.y * 32;
    const float* src = feat + (size_t)b * CCH * NPT;
    #pragma unroll
    for (int j = 0; j < 32; j += 8)
        tile[threadIdx.y + j][threadIdx.x] =
            src[(size_t)(c0 + threadIdx.y + j) * NPT + n0 + threadIdx.x];
    __syncthreads();
    #pragma unroll
    for (int j = 0; j < 32; j += 8)
        g_XT[(size_t)(b * NPT + n0 + threadIdx.y + j) * KD1 + 256 + c0 + threadIdx.x] =
            tile[threadIdx.x][threadIdx.y + j];
}

// ---------------- 3-point interpolation into XT[:, 0:256] ----------------
__global__ void k_interp() {
    const int gw = (blockIdx.x * blockDim.x + threadIdx.x) >> 5;
    const int lane = threadIdx.x & 31;
    const int b = gw >> 13;
    const size_t o3 = (size_t)gw * 3;
    const int i0 = g_idx[o3], i1 = g_idx[o3 + 1], i2 = g_idx[o3 + 2];
    const float w0 = g_wgt[o3], w1 = g_wgt[o3 + 1], w2 = g_wgt[o3 + 2];
    const float4* r0 = (const float4*)(g_fpT + ((size_t)b * MPT + i0) * CPCH);
    const float4* r1 = (const float4*)(g_fpT + ((size_t)b * MPT + i1) * CPCH);
    const float4* r2 = (const float4*)(g_fpT + ((size_t)b * MPT + i2) * CPCH);
    float4* out = (float4*)(g_XT + (size_t)gw * KD1);
    #pragma unroll
    for (int j = lane; j < 64; j += 32) {
        float4 a = r0[j], c = r1[j], d = r2[j];
        float4 r;
        r.x = fmaf(w0, a.x, fmaf(w1, c.x, w2 * d.x));
        r.y = fmaf(w0, a.y, fmaf(w1, c.y, w2 * d.y));
        r.z = fmaf(w0, a.z, fmaf(w1, c.z, w2 * d.z));
        r.w = fmaf(w0, a.w, fmaf(w1, c.w, w2 * d.w));
        out[j] = r;
    }
}

// ---------------- tcgen05 TF32 GEMM ----------------
// PHASE 1: Y1[ch][p] = XT[p][512] . w1[256][512]^T + b1    (output transposed, pre-BN)
// PHASE 2: out[b][o][n] = relu(bn1(Y1)) . w2^T + b2        (pre-BN2)
// CTA tile: M=128 points x N=256 channels, K-chunk 32 floats (=128B SW128 rows), double-buffered.
#define SM_A0 1024u
#define SM_A1 17408u
#define SM_B0 33792u
#define SM_B1 66560u
#define SM_TOTAL 99328

template <int PHASE>
__global__ void __launch_bounds__(256) k_tc_gemm(const float* __restrict__ W,
                                                 const float* __restrict__ bias,
                                                 float* __restrict__ Cout) {
    constexpr int K = (PHASE == 1) ? KD1 : OC;
    extern __shared__ char smem[];
    const int tid = threadIdx.x;
    const int m0 = blockIdx.x * 128;

#if HAS_TCGEN05
    constexpr int NT = K / 32;
    constexpr uint32_t IDESC =
        (1u << 4) | (2u << 7) | (2u << 10) | ((256u / 8) << 17) | ((128u / 16) << 24);
    const uint32_t sb = smem_u32(smem);
    const int w = tid >> 5;

    if (tid == 0) {
        asm volatile("mbarrier.init.shared.b64 [%0], 1;" :: "r"(sb + 8)  : "memory");
        asm volatile("mbarrier.init.shared.b64 [%0], 1;" :: "r"(sb + 16) : "memory");
    }
    if (w == 0)
        asm volatile("tcgen05.alloc.cta_group::1.sync.aligned.shared::cta.b32 [%0], %1;"
                     :: "r"(sb), "r"(256u) : "memory");
    __syncthreads();
    uint32_t tmem;
    asm volatile("ld.shared.b32 %0, [%1];" : "=r"(tmem) : "r"(sb));
    if (w == 0)
        asm volatile("tcgen05.relinquish_alloc_permit.cta_group::1.sync.aligned;");

    uint32_t ph0 = 0, ph1 = 0;

    for (int t = 0; t < NT; t++) {
        const int buf = t & 1;
        const uint32_t abase = buf ? SM_A1 : SM_A0;
        const uint32_t bbase = buf ? SM_B1 : SM_B0;
        if (t >= 2) {
            if (buf == 0) { mbar_wait(sb + 8,  ph0); ph0 ^= 1; }
            else          { mbar_wait(sb + 16, ph1); ph1 ^= 1; }
        }
        // ---- A tile (128 x 32 tf32), SW128-swizzled ----
        if (PHASE == 1) {
            #pragma unroll
            for (int i = 0; i < 4; i++) {
                const int f = tid + i * 256;
                const int row = f >> 3, c16 = f & 7;
                const float4 v = *(const float4*)(g_XT + (size_t)(m0 + row) * KD1 + t * 32 + c16 * 4);
                uint4 tv = make_uint4(f2tf(v.x), f2tf(v.y), f2tf(v.z), f2tf(v.w));
                *(uint4*)(smem + abase + SWZ(row * 128 + c16 * 16)) = tv;
            }
        } else {
            #pragma unroll
            for (int i = 0; i < 4; i++) {
                const int f = tid + i * 256;
                const int ch = f >> 5, pos = f & 31;
                const int gk = t * 32 + ch;
                const float a = g_bnA[gk], c = g_bnC[gk];
                float4 v = *(const float4*)(g_Y1 + (size_t)gk * NPOINTS + m0 + pos * 4);
                v.x = fmaxf(fmaf(a, v.x, c), 0.f);
                v.y = fmaxf(fmaf(a, v.y, c), 0.f);
                v.z = fmaxf(fmaf(a, v.z, c), 0.f);
                v.w = fmaxf(fmaf(a, v.w, c), 0.f);
                const int r0 = pos * 4;
                *(uint32_t*)(smem + abase + SWZ((r0 + 0) * 128 + ch * 4)) = f2tf(v.x);
                *(uint32_t*)(smem + abase + SWZ((r0 + 1) * 128 + ch * 4)) = f2tf(v.y);
                *(uint32_t*)(smem + abase + SWZ((r0 + 2) * 128 + ch * 4)) = f2tf(v.z);
                *(uint32_t*)(smem + abase + SWZ((r0 + 3) * 128 + ch * 4)) = f2tf(v.w);
            }
        }
        // ---- B tile (256 x 32 tf32) ----
        #pragma unroll
        for (int i = 0; i < 8; i++) {
            const int f = tid + i * 256;
            const int row = f >> 3, c16 = f & 7;
            const float4 v = *(const float4*)(W + (size_t)row * K + t * 32 + c16 * 4);
            uint4 tv = make_uint4(f2tf(v.x), f2tf(v.y), f2tf(v.z), f2tf(v.w));
            *(uint4*)(smem + bbase + SWZ(row * 128 + c16 * 16)) = tv;
        }
        asm volatile("fence.proxy.async.shared::cta;" ::: "memory");
        __syncthreads();
        if (w == 0 && elect1()) {
            const uint64_t ad = mk_desc(sb + abase);
            const uint64_t bd = mk_desc(sb + bbase);
            #pragma unroll
            for (int k = 0; k < 4; k++)
                mma_tf32(tmem, ad + 2 * k, bd + 2 * k, IDESC, (uint32_t)((t | k) != 0));
            asm volatile(
                "tcgen05.commit.cta_group::1.mbarrier::arrive::one.shared::cluster.b64 [%0];"
                :: "r"(sb + 8 + (uint32_t)buf * 8) : "memory");
        }
    }
    mbar_wait(sb + 8,  ph0);
    mbar_wait(sb + 16, ph1);
    asm volatile("tcgen05.fence::after_thread_sync;" ::: "memory");

    // ---- epilogue: D (128x256 fp32) from TMEM, +bias, channel-major coalesced stores ----
    const int lane = tid & 31, sub = w & 3, hf = w >> 2;
    const int mrow = m0 + sub * 32 + lane;
    #pragma unroll
    for (int cb = 0; cb < 4; cb++) {
        uint32_t r[32];
        ldtm32(r, tmem + ((uint32_t)sub << 21) + (uint32_t)(hf * 128 + cb * 32));
        asm volatile("tcgen05.wait::ld.sync.aligned;" ::: "memory");
        const int col0 = hf * 128 + cb * 32;
        if (PHASE == 1) {
            #pragma unroll
            for (int j = 0; j < 32; j++)
                g_Y1[(size_t)(col0 + j) * NPOINTS + mrow] =
                    __uint_as_float(r[j]) + __ldg(&bias[col0 + j]);
        } else {
            const int b = mrow >> 13, n = mrow & (NPT - 1);
            #pragma unroll
            for (int j = 0; j < 32; j++)
                Cout[((size_t)(b * OC + col0 + j)) * NPT + n] =
                    __uint_as_float(r[j]) + __ldg(&bias[col0 + j]);
        }
    }
    __syncthreads();
    if (tid == 0) {
        asm volatile("mbarrier.inval.shared.b64 [%0];" :: "r"(sb + 8)  : "memory");
        asm volatile("mbarrier.inval.shared.b64 [%0];" :: "r"(sb + 16) : "memory");
    }
    __syncthreads();
    if (w == 0)
        asm volatile("tcgen05.dealloc.cta_group::1.sync.aligned.b32 %0, %1;"
                     :: "r"(tmem), "r"(256u));

#else
    // ---- portable FFMA fallback (compiled for the non-'a' target only; the
    //      runtime selects the sm_103a cubin on GB300, so this never runs there) ----
    (void)smem;
    const float* Asrc = (PHASE == 1) ? g_XT : g_Y1;
    const int ty = tid >> 4, tx = tid & 15;           // 16x16 thread grid
    for (int c0 = 0; c0 < 256; c0 += 64) {
        float acc[8][4];
        #pragma unroll
        for (int i = 0; i < 8; i++)
            #pragma unroll
            for (int j = 0; j < 4; j++) acc[i][j] = 0.f;
        for (int k = 0; k < K; k++) {
            float av[8];
            if (PHASE == 1) {
                #pragma unroll
                for (int i = 0; i < 8; i++)
                    av[i] = Asrc[(size_t)(m0 + ty * 8 + i) * K + k];
            } else {
                const float a = g_bnA[k], c = g_bnC[k];
                #pragma unroll
                for (int i = 0; i < 8; i++)
                    av[i] = fmaxf(fmaf(a, Asrc[(size_t)k * NPOINTS + m0 + ty * 8 + i], c), 0.f);
            }
            float bv[4];
            #pragma unroll
            for (int j = 0; j < 4; j++)
                bv[j] = W[(size_t)(c0 + tx * 4 + j) * K + k];
            #pragma unroll
            for (int i = 0; i < 8; i++)
                #pragma unroll
                for (int j = 0; j < 4; j++)
                    acc[i][j] = fmaf(av[i], bv[j], acc[i][j]);
        }
        #pragma unroll
        for (int j = 0; j < 4; j++) {
            const int col = c0 + tx * 4 + j;
            const float bb = bias[col];
            #pragma unroll
            for (int i = 0; i < 8; i++) {
                const int mrow = m0 + ty * 8 + i;
                if (PHASE == 1) {
                    g_Y1[(size_t)col * NPOINTS + mrow] = acc[i][j] + bb;
                } else {
                    const int b = mrow >> 13, n = mrow & (NPT - 1);
                    Cout[((size_t)(b * OC + col)) * NPT + n] = acc[i][j] + bb;
                }
            }
        }
    }
#endif
}

// ---------------- BN stats reduction ----------------
// statoff==0: src = g_Y1 [256][65536], segment s covers ch = s>>3
// statoff==512: src = out [b][o][n] = [2048][8192], segment s covers ch = s&255
__global__ void k_stats(const float* __restrict__ outsrc, int statoff, int chmode) {
    const int s = blockIdx.x;
    const int ch = chmode ? (s & 255) : (s >> 3);
    const float* src = chmode ? outsrc : (const float*)g_Y1;
    const float4* p = (const float4*)(src + (size_t)s * 8192);
    float sum = 0.f, sq = 0.f;
    #pragma unroll
    for (int i = 0; i < 8; i++) {
        float4 v = p[threadIdx.x + i * 256];
        sum += v.x + v.y + v.z + v.w;
        sq = fmaf(v.x, v.x, fmaf(v.y, v.y, fmaf(v.z, v.z, fmaf(v.w, v.w, sq))));
    }
    #pragma unroll
    for (int o = 16; o > 0; o >>= 1) {
        sum += __shfl_xor_sync(0xFFFFFFFFu, sum, o);
        sq  += __shfl_xor_sync(0xFFFFFFFFu, sq, o);
    }
    __shared__ float sS[8], sQ[8];
    const int wp = threadIdx.x >> 5, l = threadIdx.x & 31;
    if (l == 0) { sS[wp] = sum; sQ[wp] = sq; }
    __syncthreads();
    if (threadIdx.x == 0) {
        float S = 0.f, Q = 0.f;
        #pragma unroll
        for (int i = 0; i < 8; i++) { S += sS[i]; Q += sQ[i]; }
        atomicAdd(&g_stats[statoff + ch], S);
        atomicAdd(&g_stats[statoff + 256 + ch], Q);
    }
}

// ---------------- BN finalize ----------------
__global__ void k_bn_final(const float* __restrict__ g, const float* __restrict__ beta, int layer) {
    const int c = threadIdx.x;
    const float invn = 1.0f / (float)NPOINTS;
    const float s = g_stats[layer * 512 + c];
    const float q = g_stats[layer * 512 + 256 + c];
    const float mean = s * invn;
    const float var = q * invn - mean * mean;
    const float a = g[c] * rsqrtf(var + BN_EPS);
    g_bnA[layer * 256 + c] = a;
    g_bnC[layer * 256 + c] = beta[c] - mean * a;
}

// ---------------- final in-place BN2 + ReLU over d_out [b][c][n] ----------------
__global__ void k_bn_relu_out(float* __restrict__ out) {
    const size_t i = (size_t)blockIdx.x * blockDim.x + threadIdx.x;
    const int ch = (int)((i >> 11) & 255);
    const float a = g_bnA[256 + ch];
    const float c = g_bnC[256 + ch];
    float4 v = ((float4*)out)[i];
    v.x = fmaxf(fmaf(a, v.x, c), 0.f);
    v.y = fmaxf(fmaf(a, v.y, c), 0.f);
    v.z = fmaxf(fmaf(a, v.z, c), 0.f);
    v.w = fmaxf(fmaf(a, v.w, c), 0.f);
    ((float4*)out)[i] = v;
}

// ---------------- launch ----------------
extern "C" void kernel_launch(void* const* d_in, const int* in_sizes, int n_in,
                              void* d_out, int out_size) {
    const float* xyz   = (const float*)d_in[0];
    const float* xyzp  = (const float*)d_in[1];
    const float* feat  = (const float*)d_in[2];
    const float* featp = (const float*)d_in[3];
    const float* w1    = (const float*)d_in[4];
    const float* b1    = (const float*)d_in[5];
    const float* g1    = (const float*)d_in[6];
    const float* be1   = (const float*)d_in[7];
    const float* w2    = (const float*)d_in[8];
    const float* b2    = (const float*)d_in[9];
    const float* g2    = (const float*)d_in[10];
    const float* be2   = (const float*)d_in[11];
    float* out = (float*)d_out;

    cudaFuncSetAttribute((const void*)k_tc_gemm<1>,
                         cudaFuncAttributeMaxDynamicSharedMemorySize, SM_TOTAL);
    cudaFuncSetAttribute((const void*)k_tc_gemm<2>,
                         cudaFuncAttributeMaxDynamicSharedMemorySize, SM_TOTAL);

    k_zero_stats<<<1, 1024>>>();
    k_three_nn<<<dim3(NPT / 256, BB), 256>>>(xyz, xyzp);
    k_transpose_fp<<<dim3(MPT / 32, CPCH / 32, BB), dim3(32, 8)>>>(featp);
    k_feat_to_XT<<<dim3(NPT / 32, CCH / 32, BB), dim3(32, 8)>>>(feat);
    k_interp<<<(NPOINTS * 32) / 256, 256>>>();

    k_tc_gemm<1><<<NPOINTS / 128, 256, SM_TOTAL>>>(w1, b1, nullptr);
    k_stats<<<2048, 256>>>(nullptr, 0, 0);
    k_bn_final<<<1, 256>>>(g1, be1, 0);

    k_tc_gemm<2><<<NPOINTS / 128, 256, SM_TOTAL>>>(w2, b2, out);
    k_stats<<<2048, 256>>>(out, 512, 1);
    k_bn_final<<<1, 256>>>(g2, be2, 1);
    k_bn_relu_out<<<(NPOINTS * OC / 4) / 256, 256>>>(out);
}